// round 4
// baseline (speedup 1.0000x reference)
#include <cuda_runtime.h>
#include <cstdint>

// ---------------------------------------------------------------------------
// Exact integer replication of the reference gate-level fp32 adder circuit.
// Words in IEEE layout: bit31=sign, [30:23]=exp, [22:0]=mant.
// Matches the circuit, NOT IEEE (truncated subnormals, subnormal mantissa path
// takes top 23 bits unshifted, big-diff at ediff>=24, exact cancel -> +0,
// overflow checked on computed_e pre-cancel).
// ---------------------------------------------------------------------------
__device__ __forceinline__ uint32_t fpadd_circuit(uint32_t ua, uint32_t ub) {
    uint32_t sa = ua >> 31, sb = ub >> 31;
    uint32_t ea = (ua >> 23) & 0xFFu, eb = (ub >> 23) & 0xFFu;
    uint32_t ma = ua & 0x7FFFFFu, mb = ub & 0x7FFFFFu;

    uint32_t ha = (ea != 0u) ? 1u : 0u;
    uint32_t hb = (eb != 0u) ? 1u : 0u;
    uint32_t eaf = ha ? ea : 1u;
    uint32_t ebf = hb ? eb : 1u;

    uint32_t Ma = (ha << 27) | (ma << 4);
    uint32_t Mb = (hb << 27) | (mb << 4);
    uint32_t maga = (ha << 23) | ma;
    uint32_t magb = (hb << 23) | mb;

    bool exp_eq = (eaf == ebf);
    bool a_ge_b = (eaf > ebf) || (exp_eq && (maga >= magb));
    bool abs_eq = exp_eq && (maga == magb);

    uint32_t ediff = a_ge_b ? (eaf - ebf) : (ebf - eaf);
    bool big = (ediff >= 24u);

    uint32_t e_max  = a_ge_b ? eaf : ebf;
    uint32_t Ml     = a_ge_b ? Ma  : Mb;
    uint32_t Ms0    = a_ge_b ? Mb  : Ma;

    uint32_t Ms;
    bool shift_sticky;
    if (big) {
        Ms = 0u;
        shift_sticky = (Ms0 != 0u);
    } else {
        Ms = Ms0 >> ediff;
        shift_sticky = (Ms0 & ((1u << ediff) - 1u)) != 0u;
    }

    bool dsign = (sa != sb);
    uint32_t s_large = a_ge_b ? sa : sb;

    uint32_t mant_res, carry;
    if (dsign) {
        mant_res = (Ml - Ms - (shift_sticky ? 1u : 0u)) & 0x0FFFFFFFu;
        carry = 0u;
    } else {
        uint32_t s = Ml + Ms;
        carry = s >> 28;
        mant_res = s & 0x0FFFFFFFu;
    }

    uint32_t lzc = mant_res ? (uint32_t)(__clz(mant_res) - 4) : 28u;
    bool underflow = (lzc >= e_max);
    uint32_t norm = (mant_res << lzc) & 0x0FFFFFFFu;

    uint32_t e_after = (e_max - lzc) & 0xFFu;
    uint32_t e_normal = underflow ? 0u : e_after;
    uint32_t final_e_pre = carry ? ((e_max + 1u) & 0xFFu) : e_normal;

    uint32_t m_pre, r_pre;
    bool st_pre;
    if (carry) {
        m_pre  = mant_res >> 5;
        r_pre  = (mant_res >> 4) & 1u;
        st_pre = (mant_res & 0xFu) != 0u;
    } else {
        m_pre  = (norm >> 4) & 0x7FFFFFu;
        r_pre  = (norm >> 3) & 1u;
        st_pre = (norm & 0x7u) != 0u;
    }
    st_pre = st_pre || shift_sticky;

    uint32_t m_sel = underflow ? (mant_res >> 5) : m_pre;
    bool do_round = (r_pre != 0u) && (st_pre || ((m_sel & 1u) != 0u)) && !underflow;

    uint32_t m24 = m_sel + (do_round ? 1u : 0u);
    uint32_t rc = (m24 >> 23) & 1u;
    uint32_t m_final = m24 & 0x7FFFFFu;
    uint32_t computed_e = (final_e_pre + rc) & 0xFFu;

    bool cancel = dsign && abs_eq;
    uint32_t out_s = cancel ? 0u : s_large;
    uint32_t out_e = cancel ? 0u : computed_e;
    uint32_t out_m = cancel ? 0u : m_final;

    bool ea1 = (ea == 0xFFu), eb1 = (eb == 0xFFu);
    bool manz = (ma != 0u),   mbnz = (mb != 0u);
    bool a_inf = ea1 && !manz, b_inf = eb1 && !mbnz;
    bool any_nan = (ea1 && manz) || (eb1 && mbnz);
    bool res_nan = any_nan || (dsign && a_inf && b_inf);
    bool ovf = (computed_e == 0xFFu);

    uint32_t out = (out_s << 31) | (out_e << 23) | out_m;
    if (a_inf || b_inf || ovf) out = (s_large << 31) | 0x7F800000u;
    if (res_nan)               out = 0x7FFFFFFFu;
    return out;
}

#define RPB   256          // rows per block (== threads)
#define SROWW 12           // smem words per row (48B: 32B data + 16B pad, 16B-aligned)

// pack 4 floats (0.0/1.0) -> word with bytes {0,1}, byte0 = first element
__device__ __forceinline__ uint32_t pack4(uint4 v) {
    uint32_t s0 = __byte_perm(v.x, v.y, 0x0073);   // b0=x.b3, b1=y.b3
    uint32_t s1 = __byte_perm(v.z, v.w, 0x0073);   // b0=z.b3, b1=w.b3
    return __byte_perm(s0, s1, 0x5410) & 0x01010101u;  // bit0 of 0x3F
}

__global__ void __launch_bounds__(256)
spike_fp32_adder_kernel(const uint4* __restrict__ A4,
                        const uint4* __restrict__ B4,
                        uint32_t* __restrict__ O,
                        int nrows) {
    __shared__ __align__(16) uint32_t sA[RPB * SROWW];
    __shared__ __align__(16) uint32_t sB[RPB * SROWW];

    const int tid = threadIdx.x;
    const int row0 = blockIdx.x * RPB;
    if (row0 >= nrows) return;
    const bool full = (row0 + RPB <= nrows);
    const int vlim = (nrows - row0) * 8;          // uint4 count in this tile

    const uint4* Af = A4 + (size_t)row0 * 8;
    const uint4* Bf = B4 + (size_t)row0 * 8;

    // ---- Phase 1: batch all 16 loads (MLP), then convert + STS ----
    uint4 ra[8], rb[8];
    if (full) {
        #pragma unroll
        for (int j = 0; j < 8; ++j) ra[j] = __ldcs(Af + j * RPB + tid);
        #pragma unroll
        for (int j = 0; j < 8; ++j) rb[j] = __ldcs(Bf + j * RPB + tid);
        #pragma unroll
        for (int j = 0; j < 8; ++j) {
            int v = j * RPB + tid;
            int w = (v >> 3) * SROWW + (v & 7);
            sA[w] = pack4(ra[j]);
            sB[w] = pack4(rb[j]);
        }
    } else {
        #pragma unroll
        for (int j = 0; j < 8; ++j) {
            int v = j * RPB + tid;
            if (v < vlim) {
                int w = (v >> 3) * SROWW + (v & 7);
                sA[w] = pack4(__ldcs(Af + v));
                sB[w] = pack4(__ldcs(Bf + v));
            }
        }
    }
    __syncthreads();

    // ---- Phase 2: assemble own row (2x LDS.128 per input), run circuit ----
    const int myrow = row0 + tid;
    uint32_t res = 0u;
    if (myrow < nrows) {
        uint4 a0 = *(const uint4*)(sA + tid * SROWW);
        uint4 a1 = *(const uint4*)(sA + tid * SROWW + 4);
        uint4 b0 = *(const uint4*)(sB + tid * SROWW);
        uint4 b1 = *(const uint4*)(sB + tid * SROWW + 4);
        uint32_t ua =  (((a0.x * 0x08040201u) >> 24) << 28)
                     | (((a0.y * 0x08040201u) >> 24) << 24)
                     | (((a0.z * 0x08040201u) >> 24) << 20)
                     | (((a0.w * 0x08040201u) >> 24) << 16)
                     | (((a1.x * 0x08040201u) >> 24) << 12)
                     | (((a1.y * 0x08040201u) >> 24) <<  8)
                     | (((a1.z * 0x08040201u) >> 24) <<  4)
                     |  ((a1.w * 0x08040201u) >> 24);
        uint32_t ub =  (((b0.x * 0x08040201u) >> 24) << 28)
                     | (((b0.y * 0x08040201u) >> 24) << 24)
                     | (((b0.z * 0x08040201u) >> 24) << 20)
                     | (((b0.w * 0x08040201u) >> 24) << 16)
                     | (((b1.x * 0x08040201u) >> 24) << 12)
                     | (((b1.y * 0x08040201u) >> 24) <<  8)
                     | (((b1.z * 0x08040201u) >> 24) <<  4)
                     |  ((b1.w * 0x08040201u) >> 24);
        res = fpadd_circuit(ua, ub);
    }

    // ---- Phase 3: shfl scatter, coalesced 16B streaming stores ----
    const int lane  = tid & 31;
    const int wrow0 = row0 + (tid & ~31);
    const int sub   = lane >> 3;                  // row-in-group-of-4
    const uint32_t e0 = (lane & 7) << 2;          // element offset in row
    #pragma unroll
    for (int k = 0; k < 8; ++k) {
        int idx  = (k << 2) + sub;
        uint32_t w = __shfl_sync(0xFFFFFFFFu, res, idx);
        int orow = wrow0 + idx;
        if (full || orow < nrows) {
            uint4 o;
            o.x = (uint32_t)(((int32_t)(w << (e0 + 0))) >> 31) & 0x3F800000u;
            o.y = (uint32_t)(((int32_t)(w << (e0 + 1))) >> 31) & 0x3F800000u;
            o.z = (uint32_t)(((int32_t)(w << (e0 + 2))) >> 31) & 0x3F800000u;
            o.w = (uint32_t)(((int32_t)(w << (e0 + 3))) >> 31) & 0x3F800000u;
            __stcs((uint4*)(O + (size_t)orow * 32 + e0), o);
        }
    }
}

extern "C" void kernel_launch(void* const* d_in, const int* in_sizes, int n_in,
                              void* d_out, int out_size) {
    const uint4* A = (const uint4*)d_in[0];
    const uint4* B = (const uint4*)d_in[1];
    uint32_t* O = (uint32_t*)d_out;

    int nrows  = in_sizes[0] / 32;                // 524288
    int blocks = (nrows + RPB - 1) / RPB;         // 2048

    spike_fp32_adder_kernel<<<blocks, 256>>>(A, B, O, nrows);
}

// round 5
// speedup vs baseline: 1.0008x; 1.0008x over previous
#include <cuda_runtime.h>
#include <cstdint>

// ---------------------------------------------------------------------------
// Exact integer replication of the reference gate-level fp32 adder circuit.
// Words in IEEE layout: bit31=sign, [30:23]=exp, [22:0]=mant.
// Matches the circuit, NOT IEEE (truncated subnormals, subnormal mantissa path
// takes top 23 bits unshifted, big-diff at ediff>=24, exact cancel -> +0,
// overflow checked on computed_e pre-cancel).
// ---------------------------------------------------------------------------
__device__ __forceinline__ uint32_t fpadd_circuit(uint32_t ua, uint32_t ub) {
    uint32_t sa = ua >> 31, sb = ub >> 31;
    uint32_t ea = (ua >> 23) & 0xFFu, eb = (ub >> 23) & 0xFFu;
    uint32_t ma = ua & 0x7FFFFFu, mb = ub & 0x7FFFFFu;

    uint32_t ha = (ea != 0u) ? 1u : 0u;
    uint32_t hb = (eb != 0u) ? 1u : 0u;
    uint32_t eaf = ha ? ea : 1u;
    uint32_t ebf = hb ? eb : 1u;

    uint32_t Ma = (ha << 27) | (ma << 4);
    uint32_t Mb = (hb << 27) | (mb << 4);
    uint32_t maga = (ha << 23) | ma;
    uint32_t magb = (hb << 23) | mb;

    bool exp_eq = (eaf == ebf);
    bool a_ge_b = (eaf > ebf) || (exp_eq && (maga >= magb));
    bool abs_eq = exp_eq && (maga == magb);

    uint32_t ediff = a_ge_b ? (eaf - ebf) : (ebf - eaf);
    bool big = (ediff >= 24u);

    uint32_t e_max  = a_ge_b ? eaf : ebf;
    uint32_t Ml     = a_ge_b ? Ma  : Mb;
    uint32_t Ms0    = a_ge_b ? Mb  : Ma;

    uint32_t Ms;
    bool shift_sticky;
    if (big) {
        Ms = 0u;
        shift_sticky = (Ms0 != 0u);
    } else {
        Ms = Ms0 >> ediff;
        shift_sticky = (Ms0 & ((1u << ediff) - 1u)) != 0u;
    }

    bool dsign = (sa != sb);
    uint32_t s_large = a_ge_b ? sa : sb;

    uint32_t mant_res, carry;
    if (dsign) {
        mant_res = (Ml - Ms - (shift_sticky ? 1u : 0u)) & 0x0FFFFFFFu;
        carry = 0u;
    } else {
        uint32_t s = Ml + Ms;
        carry = s >> 28;
        mant_res = s & 0x0FFFFFFFu;
    }

    uint32_t lzc = mant_res ? (uint32_t)(__clz(mant_res) - 4) : 28u;
    bool underflow = (lzc >= e_max);
    uint32_t norm = (mant_res << lzc) & 0x0FFFFFFFu;

    uint32_t e_after = (e_max - lzc) & 0xFFu;
    uint32_t e_normal = underflow ? 0u : e_after;
    uint32_t final_e_pre = carry ? ((e_max + 1u) & 0xFFu) : e_normal;

    uint32_t m_pre, r_pre;
    bool st_pre;
    if (carry) {
        m_pre  = mant_res >> 5;
        r_pre  = (mant_res >> 4) & 1u;
        st_pre = (mant_res & 0xFu) != 0u;
    } else {
        m_pre  = (norm >> 4) & 0x7FFFFFu;
        r_pre  = (norm >> 3) & 1u;
        st_pre = (norm & 0x7u) != 0u;
    }
    st_pre = st_pre || shift_sticky;

    uint32_t m_sel = underflow ? (mant_res >> 5) : m_pre;
    bool do_round = (r_pre != 0u) && (st_pre || ((m_sel & 1u) != 0u)) && !underflow;

    uint32_t m24 = m_sel + (do_round ? 1u : 0u);
    uint32_t rc = (m24 >> 23) & 1u;
    uint32_t m_final = m24 & 0x7FFFFFu;
    uint32_t computed_e = (final_e_pre + rc) & 0xFFu;

    bool cancel = dsign && abs_eq;
    uint32_t out_s = cancel ? 0u : s_large;
    uint32_t out_e = cancel ? 0u : computed_e;
    uint32_t out_m = cancel ? 0u : m_final;

    bool ea1 = (ea == 0xFFu), eb1 = (eb == 0xFFu);
    bool manz = (ma != 0u),   mbnz = (mb != 0u);
    bool a_inf = ea1 && !manz, b_inf = eb1 && !mbnz;
    bool any_nan = (ea1 && manz) || (eb1 && mbnz);
    bool res_nan = any_nan || (dsign && a_inf && b_inf);
    bool ovf = (computed_e == 0xFFu);

    uint32_t out = (out_s << 31) | (out_e << 23) | out_m;
    if (a_inf || b_inf || ovf) out = (s_large << 31) | 0x7F800000u;
    if (res_nan)               out = 0x7FFFFFFFu;
    return out;
}

#define RPB   256          // rows per block (== threads)
#define SROWW 12           // smem words per row (48B = 32B data + 16B pad, 16B aligned)

// pack 4 floats (0.0/1.0) -> word with one 0/1 byte per element (byte0 = elem0)
__device__ __forceinline__ uint32_t pack4(uint4 v) {
    uint32_t s0 = __byte_perm(v.x, v.y, 0x0073);        // b0=x.b3, b1=y.b3
    uint32_t s1 = __byte_perm(v.z, v.w, 0x0073);        // b0=z.b3, b1=w.b3
    return __byte_perm(s0, s1, 0x5410) & 0x01010101u;   // keep bit0 of each byte
}

__global__ void __launch_bounds__(256)
spike_fp32_adder_kernel(const uint4* __restrict__ A4,
                        const uint4* __restrict__ B4,
                        uint32_t* __restrict__ O,
                        int nrows) {
    __shared__ __align__(16) uint32_t sA[RPB * SROWW];
    __shared__ __align__(16) uint32_t sB[RPB * SROWW];

    const int tid = threadIdx.x;
    const int row0 = blockIdx.x * RPB;
    if (row0 >= nrows) return;
    const bool full = (row0 + RPB <= nrows);
    const int vlim = (nrows - row0) * 8;          // uint4 count in this tile

    // ---- Phase 1: coalesced loads, PRMT pack, STS (R2 loop structure) ----
    const uint4* Af = A4 + (size_t)row0 * 8;      // 8 uint4 per row
    const uint4* Bf = B4 + (size_t)row0 * 8;
    #pragma unroll
    for (int it = 0; it < 8; ++it) {
        int v = it * RPB + tid;                   // uint4 index in tile
        if (!full && v >= vlim) break;            // warp-uniform-ish tail
        int w = (v >> 3) * SROWW + (v & 7);
        sA[w] = pack4(Af[v]);
        sB[w] = pack4(Bf[v]);
    }
    __syncthreads();

    // ---- Phase 2: assemble own row (2x LDS.128 per input), run circuit ----
    const int myrow = row0 + tid;
    uint32_t res = 0u;
    if (myrow < nrows) {
        uint4 a0 = *(const uint4*)(sA + tid * SROWW);
        uint4 a1 = *(const uint4*)(sA + tid * SROWW + 4);
        uint4 b0 = *(const uint4*)(sB + tid * SROWW);
        uint4 b1 = *(const uint4*)(sB + tid * SROWW + 4);
        uint32_t ua =  (((a0.x * 0x08040201u) >> 24) << 28)
                     | (((a0.y * 0x08040201u) >> 24) << 24)
                     | (((a0.z * 0x08040201u) >> 24) << 20)
                     | (((a0.w * 0x08040201u) >> 24) << 16)
                     | (((a1.x * 0x08040201u) >> 24) << 12)
                     | (((a1.y * 0x08040201u) >> 24) <<  8)
                     | (((a1.z * 0x08040201u) >> 24) <<  4)
                     |  ((a1.w * 0x08040201u) >> 24);
        uint32_t ub =  (((b0.x * 0x08040201u) >> 24) << 28)
                     | (((b0.y * 0x08040201u) >> 24) << 24)
                     | (((b0.z * 0x08040201u) >> 24) << 20)
                     | (((b0.w * 0x08040201u) >> 24) << 16)
                     | (((b1.x * 0x08040201u) >> 24) << 12)
                     | (((b1.y * 0x08040201u) >> 24) <<  8)
                     | (((b1.z * 0x08040201u) >> 24) <<  4)
                     |  ((b1.w * 0x08040201u) >> 24);
        res = fpadd_circuit(ua, ub);
    }

    // ---- Phase 3: shfl scatter, coalesced 16B stores (plain STG) ----
    const int lane  = tid & 31;
    const int wrow0 = row0 + (tid & ~31);         // first row of this warp
    const int sub   = lane >> 3;                  // row within group of 4
    const uint32_t e0 = (lane & 7) << 2;          // element offset in row
    #pragma unroll
    for (int k = 0; k < 8; ++k) {
        int idx  = (k << 2) + sub;                // source lane / row in warp
        uint32_t w = __shfl_sync(0xFFFFFFFFu, res, idx);
        int orow = wrow0 + idx;
        if (full || orow < nrows) {
            uint4 o;
            o.x = (uint32_t)(((int32_t)(w << (e0 + 0))) >> 31) & 0x3F800000u;
            o.y = (uint32_t)(((int32_t)(w << (e0 + 1))) >> 31) & 0x3F800000u;
            o.z = (uint32_t)(((int32_t)(w << (e0 + 2))) >> 31) & 0x3F800000u;
            o.w = (uint32_t)(((int32_t)(w << (e0 + 3))) >> 31) & 0x3F800000u;
            *(uint4*)(O + (size_t)orow * 32 + e0) = o;
        }
    }
}

extern "C" void kernel_launch(void* const* d_in, const int* in_sizes, int n_in,
                              void* d_out, int out_size) {
    const uint4* A = (const uint4*)d_in[0];
    const uint4* B = (const uint4*)d_in[1];
    uint32_t* O = (uint32_t*)d_out;

    int nrows  = in_sizes[0] / 32;                // 524288
    int blocks = (nrows + RPB - 1) / RPB;         // 2048

    spike_fp32_adder_kernel<<<blocks, 256>>>(A, B, O, nrows);
}

// round 6
// speedup vs baseline: 1.1750x; 1.1741x over previous
#include <cuda_runtime.h>
#include <cstdint>

// ---------------------------------------------------------------------------
// Exact integer replication of the reference gate-level fp32 adder circuit.
// Words in IEEE layout: bit31=sign, [30:23]=exp, [22:0]=mant.
// Matches the circuit, NOT IEEE (truncated subnormals, subnormal mantissa path
// takes top 23 bits unshifted, big-diff at ediff>=24, exact cancel -> +0,
// overflow checked on computed_e pre-cancel).
// ---------------------------------------------------------------------------
__device__ __forceinline__ uint32_t fpadd_circuit(uint32_t ua, uint32_t ub) {
    uint32_t sa = ua >> 31, sb = ub >> 31;
    uint32_t ea = (ua >> 23) & 0xFFu, eb = (ub >> 23) & 0xFFu;
    uint32_t ma = ua & 0x7FFFFFu, mb = ub & 0x7FFFFFu;

    uint32_t ha = (ea != 0u) ? 1u : 0u;
    uint32_t hb = (eb != 0u) ? 1u : 0u;
    uint32_t eaf = ha ? ea : 1u;
    uint32_t ebf = hb ? eb : 1u;

    uint32_t Ma = (ha << 27) | (ma << 4);
    uint32_t Mb = (hb << 27) | (mb << 4);
    uint32_t maga = (ha << 23) | ma;
    uint32_t magb = (hb << 23) | mb;

    bool exp_eq = (eaf == ebf);
    bool a_ge_b = (eaf > ebf) || (exp_eq && (maga >= magb));
    bool abs_eq = exp_eq && (maga == magb);

    uint32_t ediff = a_ge_b ? (eaf - ebf) : (ebf - eaf);
    bool big = (ediff >= 24u);

    uint32_t e_max  = a_ge_b ? eaf : ebf;
    uint32_t Ml     = a_ge_b ? Ma  : Mb;
    uint32_t Ms0    = a_ge_b ? Mb  : Ma;

    uint32_t Ms;
    bool shift_sticky;
    if (big) {
        Ms = 0u;
        shift_sticky = (Ms0 != 0u);
    } else {
        Ms = Ms0 >> ediff;
        shift_sticky = (Ms0 & ((1u << ediff) - 1u)) != 0u;
    }

    bool dsign = (sa != sb);
    uint32_t s_large = a_ge_b ? sa : sb;

    uint32_t mant_res, carry;
    if (dsign) {
        mant_res = (Ml - Ms - (shift_sticky ? 1u : 0u)) & 0x0FFFFFFFu;
        carry = 0u;
    } else {
        uint32_t s = Ml + Ms;
        carry = s >> 28;
        mant_res = s & 0x0FFFFFFFu;
    }

    uint32_t lzc = mant_res ? (uint32_t)(__clz(mant_res) - 4) : 28u;
    bool underflow = (lzc >= e_max);
    uint32_t norm = (mant_res << lzc) & 0x0FFFFFFFu;

    uint32_t e_after = (e_max - lzc) & 0xFFu;
    uint32_t e_normal = underflow ? 0u : e_after;
    uint32_t final_e_pre = carry ? ((e_max + 1u) & 0xFFu) : e_normal;

    uint32_t m_pre, r_pre;
    bool st_pre;
    if (carry) {
        m_pre  = mant_res >> 5;
        r_pre  = (mant_res >> 4) & 1u;
        st_pre = (mant_res & 0xFu) != 0u;
    } else {
        m_pre  = (norm >> 4) & 0x7FFFFFu;
        r_pre  = (norm >> 3) & 1u;
        st_pre = (norm & 0x7u) != 0u;
    }
    st_pre = st_pre || shift_sticky;

    uint32_t m_sel = underflow ? (mant_res >> 5) : m_pre;
    bool do_round = (r_pre != 0u) && (st_pre || ((m_sel & 1u) != 0u)) && !underflow;

    uint32_t m24 = m_sel + (do_round ? 1u : 0u);
    uint32_t rc = (m24 >> 23) & 1u;
    uint32_t m_final = m24 & 0x7FFFFFu;
    uint32_t computed_e = (final_e_pre + rc) & 0xFFu;

    bool cancel = dsign && abs_eq;
    uint32_t out_s = cancel ? 0u : s_large;
    uint32_t out_e = cancel ? 0u : computed_e;
    uint32_t out_m = cancel ? 0u : m_final;

    bool ea1 = (ea == 0xFFu), eb1 = (eb == 0xFFu);
    bool manz = (ma != 0u),   mbnz = (mb != 0u);
    bool a_inf = ea1 && !manz, b_inf = eb1 && !mbnz;
    bool any_nan = (ea1 && manz) || (eb1 && mbnz);
    bool res_nan = any_nan || (dsign && a_inf && b_inf);
    bool ovf = (computed_e == 0xFFu);

    uint32_t out = (out_s << 31) | (out_e << 23) | out_m;
    if (a_inf || b_inf || ovf) out = (s_large << 31) | 0x7F800000u;
    if (res_nan)               out = 0x7FFFFFFFu;
    return out;
}

#define RPB   128          // rows per block (== threads)
#define SROWW 36           // smem WORDS per row: 32 data + 4 pad (144B, 16B-aligned,
                           // quarter-wavefront LDS.128 banks = t*4 mod 32 -> conflict-free)

__device__ __forceinline__ void cpasync16(uint32_t saddr, const void* gptr) {
    asm volatile("cp.async.cg.shared.global [%0], [%1], 16;" :: "r"(saddr), "l"(gptr));
}

// 4 floats (0.0/1.0 words) -> 4-bit nibble, elem0 = MSB of the nibble
__device__ __forceinline__ uint32_t nib4(uint4 v) {
    uint32_t s0 = __byte_perm(v.x, v.y, 0x0073);        // b0=x.b3, b1=y.b3
    uint32_t s1 = __byte_perm(v.z, v.w, 0x0073);
    uint32_t pk = __byte_perm(s0, s1, 0x5410) & 0x01010101u;
    return (pk * 0x08040201u) >> 24;                    // b0<<3|b1<<2|b2<<1|b3
}

__global__ void __launch_bounds__(128)
spike_fp32_adder_kernel(const uint4* __restrict__ A4,
                        const uint4* __restrict__ B4,
                        uint32_t* __restrict__ O,
                        int nrows) {
    __shared__ __align__(16) uint32_t sA[RPB * SROWW];
    __shared__ __align__(16) uint32_t sB[RPB * SROWW];

    const int tid = threadIdx.x;
    const int row0 = blockIdx.x * RPB;
    if (row0 >= nrows) return;
    const bool full = (row0 + RPB <= nrows);
    const int vlim = (nrows - row0) * 8;            // uint4 chunks in this tile

    const uint4* Af = A4 + (size_t)row0 * 8;        // 8 uint4 per row
    const uint4* Bf = B4 + (size_t)row0 * 8;

    // ---- Phase 1: pure async copy GMEM->SMEM (no registers, max MLP) ----
    const uint32_t saA = (uint32_t)__cvta_generic_to_shared(sA);
    const uint32_t saB = (uint32_t)__cvta_generic_to_shared(sB);
    #pragma unroll
    for (int it = 0; it < 8; ++it) {
        int v = it * RPB + tid;                     // chunk index in tile
        if (full || v < vlim) {
            uint32_t off = (uint32_t)(v >> 3) * (SROWW * 4) + (uint32_t)(v & 7) * 16;
            cpasync16(saA + off, Af + v);
            cpasync16(saB + off, Bf + v);
        }
    }
    asm volatile("cp.async.commit_group;");
    asm volatile("cp.async.wait_group 0;");
    __syncthreads();

    // ---- Phase 2: read own row (8x LDS.128 per input), pack, run circuit ----
    const int myrow = row0 + tid;
    uint32_t res = 0u;
    if (myrow < nrows) {
        const uint4* ra = (const uint4*)(sA + tid * SROWW);
        const uint4* rb = (const uint4*)(sB + tid * SROWW);
        uint32_t ua = 0u, ub = 0u;
        #pragma unroll
        for (int k = 0; k < 8; ++k) {
            ua |= nib4(ra[k]) << (28 - 4 * k);
            ub |= nib4(rb[k]) << (28 - 4 * k);
        }
        res = fpadd_circuit(ua, ub);
    }

    // ---- Phase 3: shfl scatter, coalesced 16B stores ----
    const int lane  = tid & 31;
    const int wrow0 = row0 + (tid & ~31);           // first row of this warp
    const int sub   = lane >> 3;                    // row within group of 4
    const uint32_t e0 = (lane & 7) << 2;            // element offset in row
    #pragma unroll
    for (int k = 0; k < 8; ++k) {
        int idx  = (k << 2) + sub;                  // source lane / row in warp
        uint32_t w = __shfl_sync(0xFFFFFFFFu, res, idx);
        int orow = wrow0 + idx;
        if (full || orow < nrows) {
            uint4 o;
            o.x = (uint32_t)(((int32_t)(w << (e0 + 0))) >> 31) & 0x3F800000u;
            o.y = (uint32_t)(((int32_t)(w << (e0 + 1))) >> 31) & 0x3F800000u;
            o.z = (uint32_t)(((int32_t)(w << (e0 + 2))) >> 31) & 0x3F800000u;
            o.w = (uint32_t)(((int32_t)(w << (e0 + 3))) >> 31) & 0x3F800000u;
            *(uint4*)(O + (size_t)orow * 32 + e0) = o;
        }
    }
}

extern "C" void kernel_launch(void* const* d_in, const int* in_sizes, int n_in,
                              void* d_out, int out_size) {
    const uint4* A = (const uint4*)d_in[0];
    const uint4* B = (const uint4*)d_in[1];
    uint32_t* O = (uint32_t*)d_out;

    int nrows  = in_sizes[0] / 32;                  // 524288
    int blocks = (nrows + RPB - 1) / RPB;           // 4096

    spike_fp32_adder_kernel<<<blocks, RPB>>>(A, B, O, nrows);
}